// round 7
// baseline (speedup 1.0000x reference)
#include <cuda_runtime.h>
#include <math.h>

#define PH 11
#define PW 11
#define SCALEF 0.0625f
#define FH 200
#define FW 200
#define NC 256
#define CH_STRIDE (FH * FW)   // 40000 elements
#define CPW 4
#define WARPS 8

struct RowInfo { int off; float ly; };   // 8B -> single LDS.64

// Block = one roi x 32 channels; warp = 4 channels; lanes 0..21 = 22 x-samples
// (px = lane>>1, sx = lane&1; lanes >=22 mirror sample 21 -> broadcast loads).
// Register cache holds X-INTERPOLATED rowA/rowB per channel; monotone row
// reuse: off==cOff full reuse, off==cOff+FW shift B->A + load rowB only,
// else load both. Scattered lo/hi LDGs span <=120B across the warp (~2
// wavefronts) - measured to be at the L1 wavefront floor for this mapping.
// The 22-sample loop is FULLY UNROLLED as 11 bin pairs; (off,ly) fused into
// one LDS.64. __launch_bounds__(256,7) caps regs at 36 for higher occupancy.
__global__ __launch_bounds__(256, 7) void roialign_maxpool_kernel(
    const float* __restrict__ feat,
    const float* __restrict__ rois,
    float* __restrict__ out)
{
    __shared__ RowInfo s_row[2 * PH];
    __shared__ float pooled[WARPS][CPW][PH][PW];

    const int k    = blockIdx.x;
    const int tid  = threadIdx.x;
    const int warp = tid >> 5;
    const int lane = tid & 31;
    const unsigned FULL = 0xffffffffu;

    const float x1 = __ldg(&rois[k * 5 + 1]) * SCALEF;
    const float y1 = __ldg(&rois[k * 5 + 2]) * SCALEF;
    const float x2 = __ldg(&rois[k * 5 + 3]) * SCALEF;
    const float y2 = __ldg(&rois[k * 5 + 4]) * SCALEF;
    const int   b  = (int)__ldg(&rois[k * 5 + 0]);

    const float bin_w = fmaxf(x2 - x1, 1.0f) * (1.0f / PW);
    const float bin_h = fmaxf(y2 - y1, 1.0f) * (1.0f / PH);

    // 22 y-sample rows once per block (input ranges guarantee no clamping)
    if (tid < 2 * PH) {
        float yc  = y1 + ((float)tid * 0.5f + 0.25f) * bin_h;
        int   ylo = (int)floorf(yc);
        s_row[tid].off = ylo * FW;
        s_row[tid].ly  = yc - (float)ylo;
    }

    // Per-lane x geometry
    const int  l  = min(lane, 2 * PW - 1);
    const int  px = l >> 1;
    const int  sx = l & 1;
    const bool store_lane = (lane < 2 * PW) && (sx == 0);

    float xc = x1 + ((float)px + 0.25f + 0.5f * (float)sx) * bin_w;
    const int   xlo = (int)floorf(xc);
    const float lx  = xc - (float)xlo;
    const float hx  = 1.0f - lx;

    const int c0 = blockIdx.y * (WARPS * CPW) + warp * CPW;
    const float* __restrict__ fbase =
        feat + ((size_t)(b * NC + c0)) * CH_STRIDE + xlo;

    __syncthreads();

    // X-interpolated row cache (rowA, rowB) per channel
    float rA0, rA1, rA2, rA3;
    float rB0, rB1, rB2, rB3;
    int   cOff = -0x40000000;

#define LOAD_ROWB(POFF)                                                        \
    {                                                                          \
        const float* __restrict__ p = fbase + (POFF);                          \
        rB0 = fmaf(lx, __ldg(p + 0 * CH_STRIDE + 1), hx * __ldg(p + 0 * CH_STRIDE)); \
        rB1 = fmaf(lx, __ldg(p + 1 * CH_STRIDE + 1), hx * __ldg(p + 1 * CH_STRIDE)); \
        rB2 = fmaf(lx, __ldg(p + 2 * CH_STRIDE + 1), hx * __ldg(p + 2 * CH_STRIDE)); \
        rB3 = fmaf(lx, __ldg(p + 3 * CH_STRIDE + 1), hx * __ldg(p + 3 * CH_STRIDE)); \
    }
#define LOAD_ROWA(POFF)                                                        \
    {                                                                          \
        const float* __restrict__ p = fbase + (POFF);                          \
        rA0 = fmaf(lx, __ldg(p + 0 * CH_STRIDE + 1), hx * __ldg(p + 0 * CH_STRIDE)); \
        rA1 = fmaf(lx, __ldg(p + 1 * CH_STRIDE + 1), hx * __ldg(p + 1 * CH_STRIDE)); \
        rA2 = fmaf(lx, __ldg(p + 2 * CH_STRIDE + 1), hx * __ldg(p + 2 * CH_STRIDE)); \
        rA3 = fmaf(lx, __ldg(p + 3 * CH_STRIDE + 1), hx * __ldg(p + 3 * CH_STRIDE)); \
    }
#define UPDATE_ROWS(OFF)                                                       \
    if ((OFF) != cOff) {                                                       \
        if ((OFF) == cOff + FW) {                                              \
            rA0 = rB0; rA1 = rB1; rA2 = rB2; rA3 = rB3;                        \
        } else {                                                               \
            LOAD_ROWA(OFF)                                                     \
        }                                                                      \
        LOAD_ROWB((OFF) + FW)                                                  \
        cOff = (OFF);                                                          \
    }

#pragma unroll
    for (int py = 0; py < PH; ++py) {
        const RowInfo i0 = s_row[2 * py];
        UPDATE_ROWS(i0.off)
        float a0 = fmaf(i0.ly, rB0 - rA0, rA0);
        float a1 = fmaf(i0.ly, rB1 - rA1, rA1);
        float a2 = fmaf(i0.ly, rB2 - rA2, rA2);
        float a3 = fmaf(i0.ly, rB3 - rA3, rA3);

        const RowInfo i1 = s_row[2 * py + 1];
        UPDATE_ROWS(i1.off)
        a0 += fmaf(i1.ly, rB0 - rA0, rA0);
        a1 += fmaf(i1.ly, rB1 - rA1, rA1);
        a2 += fmaf(i1.ly, rB2 - rA2, rA2);
        a3 += fmaf(i1.ly, rB3 - rA3, rA3);

        // fold sx pair; even lanes hold the 2x2-sample mean
        a0 += __shfl_xor_sync(FULL, a0, 1);
        a1 += __shfl_xor_sync(FULL, a1, 1);
        a2 += __shfl_xor_sync(FULL, a2, 1);
        a3 += __shfl_xor_sync(FULL, a3, 1);
        if (store_lane) {
            pooled[warp][0][py][px] = a0 * 0.25f;
            pooled[warp][1][py][px] = a1 * 0.25f;
            pooled[warp][2][py][px] = a2 * 0.25f;
            pooled[warp][3][py][px] = a3 * 0.25f;
        }
    }
    __syncwarp();

    // 3x3 stride-2 maxpool over each 11x11 pooled tile -> 5x5
    if (lane < 25) {
        const int oy = lane / 5;
        const int ox = lane % 5;
#pragma unroll
        for (int j = 0; j < CPW; ++j) {
            float m = -INFINITY;
#pragma unroll
            for (int dy = 0; dy < 3; ++dy)
#pragma unroll
                for (int dx = 0; dx < 3; ++dx)
                    m = fmaxf(m, pooled[warp][j][2 * oy + dy][2 * ox + dx]);
            out[(((size_t)k * NC + (c0 + j)) * 5 + oy) * 5 + ox] = m;
        }
    }
}

extern "C" void kernel_launch(void* const* d_in, const int* in_sizes, int n_in,
                              void* d_out, int out_size)
{
    const float* feat = (const float*)d_in[0];
    const float* rois = (const float*)d_in[1];
    float* out = (float*)d_out;

    const int K = in_sizes[1] / 5;  // 512 rois

    dim3 grid(K, NC / (WARPS * CPW));   // (512, 8)
    dim3 block(256);
    roialign_maxpool_kernel<<<grid, block>>>(feat, rois, out);
}

// round 9
// speedup vs baseline: 1.0798x; 1.0798x over previous
#include <cuda_runtime.h>
#include <math.h>

#define PH 11
#define PW 11
#define SCALEF 0.0625f
#define FH 200
#define FW 200
#define NC 256
#define CH_STRIDE (FH * FW)   // 40000 elements (160000 B, fits LDG imm offset)
#define CPW 8
#define WARPS 8               // 8 warps x 8 ch = 64 channels per block

struct RowInfo { int off; float ly; };   // 8B -> single LDS.64

// Block = one roi x 64 channels; warp = 8 channels; lanes 0..21 = 22 x-samples
// (px = lane>>1, sx = lane&1; lanes >=22 mirror sample 21 -> broadcast loads).
// Register cache holds X-INTERPOLATED rowA/rowB per channel (2 regs/ch);
// steady state = 2 FMA/ch/sample. Monotone row reuse: off==cOff full reuse,
// off==cOff+FW shift B->A + load rowB only, else load both. All loads share
// ONE base pointer with compile-time immediate channel offsets. Rolled py
// loop (full unroll + reg caps measured slower). CPW=8 halves per-channel
// amortized overhead vs CPW=4 (issue-bound regime: occ 45-83% all gave
// issue~60-70%, runtime tracks instruction count).
__global__ __launch_bounds__(256) void roialign_maxpool_kernel(
    const float* __restrict__ feat,
    const float* __restrict__ rois,
    float* __restrict__ out)
{
    __shared__ RowInfo s_row[2 * PH];
    __shared__ float pooled[WARPS][CPW][PH][PW];

    const int k    = blockIdx.x;
    const int tid  = threadIdx.x;
    const int warp = tid >> 5;
    const int lane = tid & 31;
    const unsigned FULL = 0xffffffffu;

    const float x1 = __ldg(&rois[k * 5 + 1]) * SCALEF;
    const float y1 = __ldg(&rois[k * 5 + 2]) * SCALEF;
    const float x2 = __ldg(&rois[k * 5 + 3]) * SCALEF;
    const float y2 = __ldg(&rois[k * 5 + 4]) * SCALEF;
    const int   b  = (int)__ldg(&rois[k * 5 + 0]);

    const float bin_w = fmaxf(x2 - x1, 1.0f) * (1.0f / PW);
    const float bin_h = fmaxf(y2 - y1, 1.0f) * (1.0f / PH);

    // 22 y-sample rows once per block (input ranges guarantee no clamping)
    if (tid < 2 * PH) {
        float yc  = y1 + ((float)tid * 0.5f + 0.25f) * bin_h;
        int   ylo = (int)floorf(yc);
        s_row[tid].off = ylo * FW;
        s_row[tid].ly  = yc - (float)ylo;
    }

    // Per-lane x geometry
    const int  l  = min(lane, 2 * PW - 1);
    const int  px = l >> 1;
    const int  sx = l & 1;
    const bool store_lane = (lane < 2 * PW) && (sx == 0);

    float xc = x1 + ((float)px + 0.25f + 0.5f * (float)sx) * bin_w;
    const int   xlo = (int)floorf(xc);
    const float lx  = xc - (float)xlo;
    const float hx  = 1.0f - lx;

    const int c0 = blockIdx.y * (WARPS * CPW) + warp * CPW;
    const float* __restrict__ fbase =
        feat + ((size_t)(b * NC + c0)) * CH_STRIDE + xlo;

    __syncthreads();

    // X-interpolated row cache per channel
    float rA[CPW], rB[CPW];
    int   cOff = -0x40000000;

    for (int py = 0; py < PH; ++py) {
        float a[CPW];

        // ---- sample row t = 2*py ----
        {
            const RowInfo ri = s_row[2 * py];
            const int off = ri.off;
            if (off != cOff) {                      // warp-uniform
                const float* __restrict__ p = fbase + off;
                if (off == cOff + FW) {
#pragma unroll
                    for (int j = 0; j < CPW; ++j) rA[j] = rB[j];
                } else {
#pragma unroll
                    for (int j = 0; j < CPW; ++j)
                        rA[j] = fmaf(lx, __ldg(p + j * CH_STRIDE + 1),
                                     hx * __ldg(p + j * CH_STRIDE));
                }
#pragma unroll
                for (int j = 0; j < CPW; ++j)
                    rB[j] = fmaf(lx, __ldg(p + j * CH_STRIDE + FW + 1),
                                 hx * __ldg(p + j * CH_STRIDE + FW));
                cOff = off;
            }
#pragma unroll
            for (int j = 0; j < CPW; ++j)
                a[j] = fmaf(ri.ly, rB[j] - rA[j], rA[j]);
        }

        // ---- sample row t = 2*py + 1 ----
        {
            const RowInfo ri = s_row[2 * py + 1];
            const int off = ri.off;
            if (off != cOff) {                      // warp-uniform
                const float* __restrict__ p = fbase + off;
                if (off == cOff + FW) {
#pragma unroll
                    for (int j = 0; j < CPW; ++j) rA[j] = rB[j];
                } else {
#pragma unroll
                    for (int j = 0; j < CPW; ++j)
                        rA[j] = fmaf(lx, __ldg(p + j * CH_STRIDE + 1),
                                     hx * __ldg(p + j * CH_STRIDE));
                }
#pragma unroll
                for (int j = 0; j < CPW; ++j)
                    rB[j] = fmaf(lx, __ldg(p + j * CH_STRIDE + FW + 1),
                                 hx * __ldg(p + j * CH_STRIDE + FW));
                cOff = off;
            }
#pragma unroll
            for (int j = 0; j < CPW; ++j)
                a[j] += fmaf(ri.ly, rB[j] - rA[j], rA[j]);
        }

        // fold sx pair; even lanes hold the 2x2-sample mean
#pragma unroll
        for (int j = 0; j < CPW; ++j)
            a[j] += __shfl_xor_sync(FULL, a[j], 1);
        if (store_lane) {
#pragma unroll
            for (int j = 0; j < CPW; ++j)
                pooled[warp][j][py][px] = a[j] * 0.25f;
        }
    }
    __syncwarp();

    // 3x3 stride-2 maxpool over each 11x11 pooled tile -> 5x5
    if (lane < 25) {
        const int oy = lane / 5;
        const int ox = lane % 5;
#pragma unroll
        for (int j = 0; j < CPW; ++j) {
            float m = -INFINITY;
#pragma unroll
            for (int dy = 0; dy < 3; ++dy)
#pragma unroll
                for (int dx = 0; dx < 3; ++dx)
                    m = fmaxf(m, pooled[warp][j][2 * oy + dy][2 * ox + dx]);
            out[(((size_t)k * NC + (c0 + j)) * 5 + oy) * 5 + ox] = m;
        }
    }
}

extern "C" void kernel_launch(void* const* d_in, const int* in_sizes, int n_in,
                              void* d_out, int out_size)
{
    const float* feat = (const float*)d_in[0];
    const float* rois = (const float*)d_in[1];
    float* out = (float*)d_out;

    const int K = in_sizes[1] / 5;  // 512 rois

    dim3 grid(K, NC / (WARPS * CPW));   // (512, 4)
    dim3 block(256);
    roialign_maxpool_kernel<<<grid, block>>>(feat, rois, out);
}